// round 1
// baseline (speedup 1.0000x reference)
#include <cuda_runtime.h>

#define NB 32
#define S 64
#define S2 (S*S)
#define S3 (S*S*S)
#define NPTS 65536
#define GRID_ELEMS (NB*S3)

// 21-tap Gaussian, sigma=3, normalized (computed in double precision)
#define CONV_W { 5.143166e-04f, 1.477931e-03f, 3.800325e-03f, 8.744478e-03f, \
                 1.800486e-02f, 3.317359e-02f, 5.469392e-02f, 8.069228e-02f, \
                 1.065293e-01f, 1.258494e-01f, 1.330392e-01f, 1.258494e-01f, \
                 1.065293e-01f, 8.069228e-02f, 5.469392e-02f, 3.317359e-02f, \
                 1.800486e-02f, 8.744478e-03f, 3.800325e-03f, 1.477931e-03f, \
                 5.143166e-04f }

__device__ float g_vox[GRID_ELEMS];   // scatter target / convY output
__device__ float g_tmp[GRID_ELEMS];   // convX output

// ---------------------------------------------------------------------------
// Zero the voxel grid
// ---------------------------------------------------------------------------
__global__ void k_zero() {
    float4* p = reinterpret_cast<float4*>(g_vox);
    int n4 = GRID_ELEMS / 4;
    for (int i = blockIdx.x * blockDim.x + threadIdx.x; i < n4;
         i += gridDim.x * blockDim.x)
        p[i] = make_float4(0.f, 0.f, 0.f, 0.f);
}

// ---------------------------------------------------------------------------
// Rotate points + trilinear scatter (atomic)
// pc_t[b,n,j] = sum_i pc[b,n,i] * rot[b,j,i]
// ---------------------------------------------------------------------------
__global__ void k_scatter(const float* __restrict__ pc,
                          const float* __restrict__ rot) {
    int tid = blockIdx.x * 256 + threadIdx.x;       // 2M threads
    int b = tid >> 16;                              // 65536 pts per batch, 256/blk
    __shared__ float R[9];
    if (threadIdx.x < 9) R[threadIdx.x] = rot[b * 9 + threadIdx.x];
    __syncthreads();

    size_t pbase = (size_t)tid * 3;
    float px = pc[pbase + 0];
    float py = pc[pbase + 1];
    float pz = pc[pbase + 2];

    float tx = px * R[0] + py * R[1] + pz * R[2];
    float ty = px * R[3] + py * R[4] + pz * R[5];
    float tz = px * R[6] + py * R[7] + pz * R[8];

    float gx = (tx + 0.5f) * 63.0f;
    float gy = (ty + 0.5f) * 63.0f;
    float gz = (tz + 0.5f) * 63.0f;
    float fx = floorf(gx), fy = floorf(gy), fz = floorf(gz);
    int ix = (int)fx, iy = (int)fy, iz = (int)fz;
    float ax = gx - fx, ay = gy - fy, az = gz - fz;

    float wx[2] = {1.0f - ax, ax};
    float wy[2] = {1.0f - ay, ay};
    float wz[2] = {1.0f - az, az};

    float* base = g_vox + (size_t)b * S3;
#pragma unroll
    for (int c = 0; c < 8; c++) {
        int dx = c & 1, dy = (c >> 1) & 1, dz = c >> 2;
        int X = ix + dx, Y = iy + dy, Z = iz + dz;
        if ((unsigned)X < S && (unsigned)Y < S && (unsigned)Z < S) {
            atomicAdd(base + Z * S2 + Y * S + X, wx[dx] * wy[dy] * wz[dz]);
        }
    }
}

// ---------------------------------------------------------------------------
// Conv along X (with clip of raw voxels to [0,1] on load). One block per (b,z).
// smem row stride 85 (odd) -> conflict-free for warp-stride-16 window reads.
// ---------------------------------------------------------------------------
__global__ void k_convx() {
    const float W[21] = CONV_W;
    int bz = blockIdx.x;
    const float* src = g_vox + (size_t)bz * S2;
    float*       dst = g_tmp + (size_t)bz * S2;
    __shared__ float s[S * 85];
    int t = threadIdx.x;

    for (int i = t; i < S * 85; i += 256) s[i] = 0.0f;
    __syncthreads();
    for (int i = t; i < S2; i += 256) {
        int y = i >> 6, x = i & 63;
        float v = src[i];
        s[y * 85 + x + 10] = fminf(fmaxf(v, 0.0f), 1.0f);
    }
    __syncthreads();

    int y  = t & 63;            // warp = 32 consecutive y
    int x0 = (t >> 6) * 16;     // 16-wide x tile
    const float* row = s + y * 85 + x0;
    float win[36];
#pragma unroll
    for (int j = 0; j < 36; j++) win[j] = row[j];

    float o[16];
#pragma unroll
    for (int j = 0; j < 16; j++) {
        float a = 0.0f;
#pragma unroll
        for (int k = 0; k < 21; k++) a = fmaf(win[j + k], W[k], a);
        o[j] = a;
    }
    float4* d4 = reinterpret_cast<float4*>(dst + y * S + x0);
#pragma unroll
    for (int j = 0; j < 4; j++)
        d4[j] = make_float4(o[4*j], o[4*j+1], o[4*j+2], o[4*j+3]);
}

// ---------------------------------------------------------------------------
// Conv along Y. One block per (b,z). Warp reads stride-1 in x -> conflict-free.
// ---------------------------------------------------------------------------
__global__ void k_convy() {
    const float W[21] = CONV_W;
    int bz = blockIdx.x;
    const float* src = g_tmp + (size_t)bz * S2;
    float*       dst = g_vox + (size_t)bz * S2;
    __shared__ float s[84 * S];     // (y+10)*64 + x
    int t = threadIdx.x;

    for (int i = t; i < 10 * S; i += 256) { s[i] = 0.0f; s[74 * S + i] = 0.0f; }
    for (int i = t; i < S2; i += 256) s[10 * S + i] = src[i];
    __syncthreads();

    int x  = t & 63;            // warp = 32 consecutive x
    int y0 = (t >> 6) * 16;
    float win[36];
#pragma unroll
    for (int j = 0; j < 36; j++) win[j] = s[(y0 + j) * S + x];

#pragma unroll
    for (int j = 0; j < 16; j++) {
        float a = 0.0f;
#pragma unroll
        for (int k = 0; k < 21; k++) a = fmaf(win[j + k], W[k], a);
        dst[(y0 + j) * S + x] = a;
    }
}

// ---------------------------------------------------------------------------
// Conv along Z + scale + clip + DRC product + flip. One block per (b,y).
// out[b, 63-y, x] = 1 - prod_z (1 - clip(scale_b * convz[z,x]))
// ---------------------------------------------------------------------------
__global__ void k_convz(const float* __restrict__ scale,
                        float* __restrict__ out) {
    const float W[21] = CONV_W;
    int by = blockIdx.x;
    int b = by >> 6, y = by & 63;
    const float* src = g_vox + (size_t)b * S3 + y * S;   // + z*S2 + x
    __shared__ float s[84 * S];      // (z+10)*64 + x
    __shared__ float part[4][S];
    int t = threadIdx.x;

    for (int i = t; i < 10 * S; i += 256) { s[i] = 0.0f; s[74 * S + i] = 0.0f; }
    for (int i = t; i < S2; i += 256) {
        int z = i >> 6, x = i & 63;
        s[10 * S + i] = src[(size_t)z * S2 + x];
    }
    __syncthreads();

    float sc = scale[b];
    int x  = t & 63;
    int z0 = (t >> 6) * 16;
    float win[36];
#pragma unroll
    for (int j = 0; j < 36; j++) win[j] = s[(z0 + j) * S + x];

    float T = 1.0f;
#pragma unroll
    for (int j = 0; j < 16; j++) {
        float a = 0.0f;
#pragma unroll
        for (int k = 0; k < 21; k++) a = fmaf(win[j + k], W[k], a);
        a = fminf(fmaxf(a * sc, 0.0f), 1.0f);
        T *= (1.0f - a);
    }
    part[t >> 6][x] = T;
    __syncthreads();
    if (t < 64) {
        float Tt = part[0][x] * part[1][x] * part[2][x] * part[3][x];
        out[(size_t)b * S2 + (63 - y) * S + x] = 1.0f - Tt;
    }
}

// ---------------------------------------------------------------------------
extern "C" void kernel_launch(void* const* d_in, const int* in_sizes, int n_in,
                              void* d_out, int out_size) {
    const float* pc    = (const float*)d_in[0];
    const float* rot   = (const float*)d_in[1];
    const float* scale = (const float*)d_in[2];
    float* out = (float*)d_out;

    k_zero<<<2048, 256>>>();
    k_scatter<<<NB * NPTS / 256, 256>>>(pc, rot);
    k_convx<<<NB * S, 256>>>();
    k_convy<<<NB * S, 256>>>();
    k_convz<<<NB * S, 256>>>(scale, out);
}

// round 3
// speedup vs baseline: 1.1109x; 1.1109x over previous
#include <cuda_runtime.h>

#define NB 32
#define S 64
#define S2 (S*S)
#define S3 (S*S*S)
#define NPTS 65536
#define GRID_ELEMS (NB*S3)

// 21-tap Gaussian, sigma=3, normalized (computed in double precision)
__device__ __constant__ float W[21] = {
    5.143166e-04f, 1.477931e-03f, 3.800325e-03f, 8.744478e-03f,
    1.800486e-02f, 3.317359e-02f, 5.469392e-02f, 8.069228e-02f,
    1.065293e-01f, 1.258494e-01f, 1.330392e-01f, 1.258494e-01f,
    1.065293e-01f, 8.069228e-02f, 5.469392e-02f, 3.317359e-02f,
    1.800486e-02f, 8.744478e-03f, 3.800325e-03f, 1.477931e-03f,
    5.143166e-04f };

__device__ float g_vox[GRID_ELEMS];   // scatter target
__device__ float g_tmp[GRID_ELEMS];   // convXY output

// Value-stationary 21-tap conv: 16 accumulators, each input read once.
// `m` = window position 0..35; contributes to outputs j with 0<=m-j<=20.
#define CONV16(LOADEXPR, OUTSTMT)                                        \
    {                                                                    \
        float o[16];                                                     \
        _Pragma("unroll") for (int j = 0; j < 16; j++) o[j] = 0.0f;      \
        _Pragma("unroll") for (int m = 0; m < 36; m++) {                 \
            float v = (LOADEXPR);                                        \
            const int jlo = (m > 20) ? (m - 20) : 0;                     \
            const int jhi = (m < 15) ? m : 15;                           \
            _Pragma("unroll") for (int j = jlo; j <= jhi; j++)           \
                o[j] = fmaf(v, W[m - j], o[j]);                          \
        }                                                                \
        _Pragma("unroll") for (int j = 0; j < 16; j++) { OUTSTMT; }      \
    }

// ---------------------------------------------------------------------------
// Zero the voxel grid
// ---------------------------------------------------------------------------
__global__ void k_zero() {
    float4* p = reinterpret_cast<float4*>(g_vox);
    int n4 = GRID_ELEMS / 4;
    for (int i = blockIdx.x * blockDim.x + threadIdx.x; i < n4;
         i += gridDim.x * blockDim.x)
        p[i] = make_float4(0.f, 0.f, 0.f, 0.f);
}

// ---------------------------------------------------------------------------
// Rotate points + trilinear scatter (atomic). Coalesced scalar point loads
// staged through smem (no alignment assumption on pc).
// ---------------------------------------------------------------------------
__global__ void k_scatter(const float* __restrict__ pc,
                          const float* __restrict__ rot) {
    int t = threadIdx.x;
    int b = blockIdx.x >> 8;                     // 256 blocks per batch
    __shared__ float R[9];
    __shared__ float sp[768];                    // 256 points * 3
    if (t < 9) R[t] = rot[b * 9 + t];
    const float* pblk = pc + (size_t)blockIdx.x * 768;
    sp[t]       = pblk[t];
    sp[t + 256] = pblk[t + 256];
    sp[t + 512] = pblk[t + 512];
    __syncthreads();

    float px = sp[t * 3 + 0];
    float py = sp[t * 3 + 1];
    float pz = sp[t * 3 + 2];

    float tx = fmaf(px, R[0], fmaf(py, R[1], pz * R[2]));
    float ty = fmaf(px, R[3], fmaf(py, R[4], pz * R[5]));
    float tz = fmaf(px, R[6], fmaf(py, R[7], pz * R[8]));

    float gx = (tx + 0.5f) * 63.0f;
    float gy = (ty + 0.5f) * 63.0f;
    float gz = (tz + 0.5f) * 63.0f;
    float fx = floorf(gx), fy = floorf(gy), fz = floorf(gz);
    int ix = (int)fx, iy = (int)fy, iz = (int)fz;
    float ax = gx - fx, ay = gy - fy, az = gz - fz;

    float wx[2] = {1.0f - ax, ax};
    float wy[2] = {1.0f - ay, ay};
    float wz[2] = {1.0f - az, az};

    float* base = g_vox + (size_t)b * S3;
#pragma unroll
    for (int c = 0; c < 8; c++) {
        int dx = c & 1, dy = (c >> 1) & 1, dz = c >> 2;
        int X = ix + dx, Y = iy + dy, Z = iz + dz;
        if ((unsigned)X < S && (unsigned)Y < S && (unsigned)Z < S) {
            atomicAdd(base + Z * S2 + Y * S + X, wx[dx] * wy[dy] * wz[dz]);
        }
    }
}

// ---------------------------------------------------------------------------
// Fused conv along X then Y (clip raw voxels on load). One block per (b,z).
// A: x-padded rows, stride 85 (odd) -> conflict-free window reads.
// B: y-padded, row stride 65 (odd)  -> conflict-free stride-64-ish access.
// ---------------------------------------------------------------------------
__global__ void __launch_bounds__(256) k_convxy() {
    int bz = blockIdx.x;
    const float* src = g_vox + (size_t)bz * S2;
    float*       dst = g_tmp + (size_t)bz * S2;
    __shared__ float A[S * 85];      // [y][x+10], x pads zeroed
    __shared__ float B[84 * 65];     // [y+10][x], y pads zeroed
    int t = threadIdx.x;

    for (int i = t; i < S * 85; i += 256) A[i] = 0.0f;
    // zero B's pad rows (rows 0..9 and 74..83)
    for (int i = t; i < 10 * 65; i += 256) { B[i] = 0.0f; B[74 * 65 + i] = 0.0f; }
    __syncthreads();
    for (int i = t; i < S2; i += 256) {
        int y = i >> 6, x = i & 63;
        float v = src[i];
        A[y * 85 + x + 10] = fminf(fmaxf(v, 0.0f), 1.0f);
    }
    __syncthreads();

    {   // conv X: warp = 32 consecutive y (stride 85 -> conflict-free)
        int y  = t & 63;
        int x0 = (t >> 6) * 16;
        const float* row = A + y * 85 + x0;
        float* brow = B + (y + 10) * 65 + x0;
        CONV16(row[m], brow[j] = o[j]);
    }
    __syncthreads();

    {   // conv Y: warp = 32 consecutive x (stride 1 -> conflict-free)
        int x  = t & 63;
        int y0 = (t >> 6) * 16;
        const float* col = B + y0 * 65 + x;
        float* d = dst + y0 * S + x;
        CONV16(col[m * 65], d[j * S] = o[j]);
    }
}

// ---------------------------------------------------------------------------
// Conv along Z + scale + clip + DRC product + flip. One block per (b,y).
// out[b, 63-y, x] = 1 - prod_z (1 - clip(scale_b * convz[z,x]))
// ---------------------------------------------------------------------------
__global__ void __launch_bounds__(256) k_convz(const float* __restrict__ scale,
                                               float* __restrict__ out) {
    int by = blockIdx.x;
    int b = by >> 6, y = by & 63;
    const float* src = g_tmp + (size_t)b * S3 + y * S;   // + z*S2 + x
    __shared__ float Bz[84 * 65];    // [z+10][x]
    __shared__ float part[4][S];
    int t = threadIdx.x;

    for (int i = t; i < 10 * 65; i += 256) { Bz[i] = 0.0f; Bz[74 * 65 + i] = 0.0f; }
    for (int i = t; i < S2; i += 256) {
        int z = i >> 6, x = i & 63;
        Bz[(z + 10) * 65 + x] = src[(size_t)z * S2 + x];
    }
    __syncthreads();

    float sc = scale[b];
    int x  = t & 63;
    int z0 = (t >> 6) * 16;
    const float* col = Bz + z0 * 65 + x;

    float T = 1.0f;
    CONV16(col[m * 65],
           { float a = fminf(fmaxf(o[j] * sc, 0.0f), 1.0f); T *= (1.0f - a); });

    part[t >> 6][x] = T;
    __syncthreads();
    if (t < 64) {
        float Tt = part[0][x] * part[1][x] * part[2][x] * part[3][x];
        out[(size_t)b * S2 + (63 - y) * S + x] = 1.0f - Tt;
    }
}

// ---------------------------------------------------------------------------
extern "C" void kernel_launch(void* const* d_in, const int* in_sizes, int n_in,
                              void* d_out, int out_size) {
    const float* pc    = (const float*)d_in[0];
    const float* rot   = (const float*)d_in[1];
    const float* scale = (const float*)d_in[2];
    float* out = (float*)d_out;

    k_zero<<<2048, 256>>>();
    k_scatter<<<NB * NPTS / 256, 256>>>(pc, rot);
    k_convxy<<<NB * S, 256>>>();
    k_convz<<<NB * S, 256>>>(scale, out);
}